// round 7
// baseline (speedup 1.0000x reference)
#include <cuda_runtime.h>
#include <cuda_bf16.h>
#include <cstdint>
#include <cstddef>

// ---------------------------------------------------------------------------
// Problem constants
// ---------------------------------------------------------------------------
#define NTYPES 6
#define HID    256
#define DV     128
#define CCH    64
#define IMH    192
#define IMW    192
#define GARM   24
#define MAXTILES 816   // sum ceil(M_t/128) <= 809; pad a little

// ---------------------------------------------------------------------------
// Static device scratch. Blob = the exact SMEM image a GEMM tile load wants:
//  A tile image: 128 rows x 64 bf16 (128B/row), SW128-swizzled -> 16KB = 1024 uint4
//  B tile image: 256 rows (n) x 64 bf16 (k)  -> 32KB = 2048 uint4   (B^T layout)
// ---------------------------------------------------------------------------
__device__ float g_garf[GARM * CCH];
__device__ float g_bias[GARM * HID];                       // garf @ W1[128:192]
__device__ uint4 g_fa_hi[(size_t)MAXTILES * 2 * 1024];     // x_verts only (K=128)
__device__ uint4 g_fa_lo[(size_t)MAXTILES * 2 * 1024];
__device__ uint4 g_h1_hi[(size_t)MAXTILES * 4 * 1024];
__device__ uint4 g_h1_lo[(size_t)MAXTILES * 4 * 1024];
__device__ uint4 g_B1_hi[6 * 2 * 2048];                    // W1[:128] only
__device__ uint4 g_B1_lo[6 * 2 * 2048];
__device__ uint4 g_B2_hi[6 * 4 * 2048];
__device__ uint4 g_B2_lo[6 * 4 * 2048];

struct P {
    const int* idx[NTYPES];
    int M[NTYPES];
    int rowOff[NTYPES + 1];
    int tileOff[NTYPES + 1];   // cumsum of ceil(M/128)
};

// ---------------------------------------------------------------------------
// Helpers (base-arch PTX only: ldmatrix / mma.sync / cp.async — all sm_80+)
// ---------------------------------------------------------------------------
__device__ __forceinline__ uint32_t smem_u32(const void* p) {
    uint32_t a;
    asm("{ .reg .u64 t; cvta.to.shared.u64 t, %1; cvt.u32.u64 %0, t; }" : "=r"(a) : "l"(p));
    return a;
}
#define SW128(x) ((x) ^ (((x) >> 3) & 0x70))

__device__ __forceinline__ void cpa16(uint32_t s, const void* g) {
    asm volatile("cp.async.cg.shared.global [%0], [%1], 16;" :: "r"(s), "l"(g));
}
#define CP_COMMIT() asm volatile("cp.async.commit_group;" ::: "memory")
#define CP_WAIT0()  asm volatile("cp.async.wait_group 0;" ::: "memory")
#define CP_WAIT1()  asm volatile("cp.async.wait_group 1;" ::: "memory")

__device__ __forceinline__ void ldm_x4(uint32_t* r, uint32_t addr) {
    asm volatile("ldmatrix.sync.aligned.m8n8.x4.shared.b16 {%0,%1,%2,%3}, [%4];"
                 : "=r"(r[0]), "=r"(r[1]), "=r"(r[2]), "=r"(r[3]) : "r"(addr));
}
__device__ __forceinline__ void mma16816(float* d, const uint32_t* a, uint32_t b0, uint32_t b1) {
    asm volatile(
        "mma.sync.aligned.m16n8k16.row.col.f32.bf16.bf16.f32 "
        "{%0,%1,%2,%3},{%4,%5,%6,%7},{%8,%9},{%0,%1,%2,%3};"
        : "+f"(d[0]), "+f"(d[1]), "+f"(d[2]), "+f"(d[3])
        : "r"(a[0]), "r"(a[1]), "r"(a[2]), "r"(a[3]), "r"(b0), "r"(b1));
}
__device__ __forceinline__ void sts32(uint32_t addr, uint32_t v) {
    asm volatile("st.shared.b32 [%0], %1;" :: "r"(addr), "r"(v) : "memory");
}

// bf16 hi/lo split + pack
__device__ __forceinline__ void bsplit(float x, uint16_t& h, uint16_t& l) {
    __nv_bfloat16 hb = __float2bfloat16_rn(x);
    float hf = __bfloat162float(hb);
    __nv_bfloat16 lb = __float2bfloat16_rn(x - hf);
    h = *reinterpret_cast<uint16_t*>(&hb);
    l = *reinterpret_cast<uint16_t*>(&lb);
}
__device__ __forceinline__ uint32_t pk16(uint16_t a, uint16_t b) {
    return (uint32_t)a | ((uint32_t)b << 16);
}
__device__ __forceinline__ void split8(const float* v, uint4& hq, uint4& lq) {
    uint16_t h[8], l[8];
    #pragma unroll
    for (int i = 0; i < 8; i++) bsplit(v[i], h[i], l[i]);
    hq = make_uint4(pk16(h[0], h[1]), pk16(h[2], h[3]), pk16(h[4], h[5]), pk16(h[6], h[7]));
    lq = make_uint4(pk16(l[0], l[1]), pk16(l[2], l[3]), pk16(l[4], l[5]), pk16(l[6], l[7]));
}

// ---------------------------------------------------------------------------
// Kernel 1: ROI-align + mean pool -> g_garf
// ---------------------------------------------------------------------------
__global__ void roi_garf_kernel(const float* __restrict__ imgs,
                                const float* __restrict__ pros,
                                const int* __restrict__ imgbatch) {
    int g = blockIdx.x, c = blockIdx.y, tid = threadIdx.x;
    int b = imgbatch[g];
    float px = pros[2 * g + 0], py = pros[2 * g + 1];
    const float* im = imgs + ((size_t)(b * CCH + c)) * (IMH * IMW);
    float sum = 0.0f;
    #pragma unroll
    for (int s = tid; s < 1024; s += 256) {
        int i = s >> 5, j = s & 31;
        float y = py - 16.0f + (float)i + 0.5f;
        float x = px - 16.0f + (float)j + 0.5f;
        float yf = floorf(y), xf = floorf(x);
        float wy = y - yf, wx = x - xf;
        int y0 = (int)yf, x0 = (int)xf, y1, x1;
        y1 = min(max(y0 + 1, 0), IMH - 1); x1 = min(max(x0 + 1, 0), IMW - 1);
        y0 = min(max(y0, 0), IMH - 1);     x0 = min(max(x0, 0), IMW - 1);
        float v00 = im[y0 * IMW + x0], v01 = im[y0 * IMW + x1];
        float v10 = im[y1 * IMW + x0], v11 = im[y1 * IMW + x1];
        sum += (1.0f - wy) * ((1.0f - wx) * v00 + wx * v01)
             +          wy * ((1.0f - wx) * v10 + wx * v11);
    }
    __shared__ float red[256];
    red[tid] = sum;
    __syncthreads();
    #pragma unroll
    for (int off = 128; off > 0; off >>= 1) {
        if (tid < off) red[tid] += red[tid + off];
        __syncthreads();
    }
    if (tid == 0) g_garf[g * CCH + c] = red[0] * (1.0f / 1024.0f);
}

// ---------------------------------------------------------------------------
// Kernel 1b: per-garment layer-1 bias: bias[g] = garf[g] @ W1[t(g)][128:192].
// grid (6, 4), 512 threads: n = tid&255 (output col), kh = tid>>8 (k half).
// ---------------------------------------------------------------------------
__global__ void bias_kernel(const float* __restrict__ W1,
                            const int* __restrict__ gov, P p) {
    int t = blockIdx.x, j = blockIdx.y, tid = threadIdx.x;
    int n = tid & 255, kh = tid >> 8;
    int g = gov[p.idx[t][j * (p.M[t] >> 2)]];
    __shared__ float gf[CCH];
    __shared__ float part[512];
    if (tid < CCH) gf[tid] = g_garf[g * CCH + tid];
    __syncthreads();
    const float* w = W1 + ((size_t)t * 192 + DV + kh * 32) * HID + n;
    float s = 0.0f;
    #pragma unroll 8
    for (int k = 0; k < 32; k++) s += gf[kh * 32 + k] * w[(size_t)k * HID];
    part[tid] = s;
    __syncthreads();
    if (kh == 0) g_bias[g * HID + n] = part[n] + part[n + 256];
}

// ---------------------------------------------------------------------------
// Kernel 2: weight images. grid (6, 6): y<2 -> layer1 chunk y, else layer2 y-2.
// ---------------------------------------------------------------------------
__global__ void wimg_kernel(const float* __restrict__ W1, const float* __restrict__ W2) {
    int t = blockIdx.x, cc = blockIdx.y, n = threadIdx.x;
    const float* W;
    uint4 *dh, *dl;
    int c;
    if (cc < 2) {
        c = cc;
        W = W1 + (size_t)t * 192 * 256;
        dh = g_B1_hi + (size_t)(t * 2 + c) * 2048;
        dl = g_B1_lo + (size_t)(t * 2 + c) * 2048;
    } else {
        c = cc - 2;
        W = W2 + (size_t)t * 256 * 256;
        dh = g_B2_hi + (size_t)(t * 4 + c) * 2048;
        dl = g_B2_lo + (size_t)(t * 4 + c) * 2048;
    }
    #pragma unroll
    for (int g4 = 0; g4 < 8; g4++) {
        float v[8];
        #pragma unroll
        for (int i = 0; i < 8; i++) v[i] = W[(size_t)(c * 64 + g4 * 8 + i) * 256 + n];
        uint4 hq, lq;
        split8(v, hq, lq);
        uint32_t sw = SW128((uint32_t)(n * 128 + g4 * 16));
        dh[sw >> 4] = hq;
        dl[sw >> 4] = lq;
    }
}

// ---------------------------------------------------------------------------
// Kernel 3: feature images (x_verts only). grid = tiles, 128 threads.
// ---------------------------------------------------------------------------
__global__ void featimg_kernel(const float* __restrict__ xv, P p) {
    int mt = blockIdx.x, r = threadIdx.x;
    int t = 0;
    while (t < NTYPES - 1 && mt >= p.tileOff[t + 1]) t++;
    int grow = (mt - p.tileOff[t]) * 128 + r;
    bool valid = grow < p.M[t];
    int v = valid ? p.idx[t][grow] : 0;
    #pragma unroll
    for (int c = 0; c < 2; c++) {
        const float* src = xv + (size_t)v * DV + c * 64;
        uint4* dh = g_fa_hi + (size_t)(mt * 2 + c) * 1024;
        uint4* dl = g_fa_lo + (size_t)(mt * 2 + c) * 1024;
        #pragma unroll
        for (int g4 = 0; g4 < 8; g4++) {
            float v8[8];
            if (valid) {
                float4 f0 = *(const float4*)(src + g4 * 8);
                float4 f1 = *(const float4*)(src + g4 * 8 + 4);
                v8[0] = f0.x; v8[1] = f0.y; v8[2] = f0.z; v8[3] = f0.w;
                v8[4] = f1.x; v8[5] = f1.y; v8[6] = f1.z; v8[7] = f1.w;
            } else {
                #pragma unroll
                for (int i = 0; i < 8; i++) v8[i] = 0.0f;
            }
            uint4 hq, lq;
            split8(v8, hq, lq);
            uint32_t sw = SW128((uint32_t)(r * 128 + g4 * 16));
            dh[sw >> 4] = hq;
            dl[sw >> 4] = lq;
        }
    }
}

// ---------------------------------------------------------------------------
// Kernel 4/5: mma.sync GEMM with B-resident smem + small A-only stages.
// CTA = 64x64 output tile, 128 threads, 4 warps (2x2 grid of 32x32 tiles).
// grid = (4 n-quarters [fastest -> A shared in L2], 2*tiles m-halves).
// ALL B chunks preloaded to smem once (MODE1 32KB, MODE2 64KB);
// A streamed in a 2-slot ring of 16KB stages (depth-1 prefetch covers fetch).
// 3-pass bf16 hi/lo split, fp32 accum.
// MODE 1: A = feat blobs (2 chunks, K=128), acc init = per-garment bias,
//         epilogue relu+split -> h1 blob chunk 'by'.
// MODE 2: A = h1 blobs (4 chunks), epilogue relu + fused layer3 + atomic scatter.
// smem: [B: CHUNKS*16KB][A ring: 2*16KB]  (+1KB align)
// ---------------------------------------------------------------------------
template <int CHUNKS, int MODE>
__global__ __launch_bounds__(128, 2)
void gemm_mma_kernel(const float* __restrict__ W3,
                     const int* __restrict__ gov,
                     float* __restrict__ out, P p) {
    extern __shared__ char dsm[];
    int tid = threadIdx.x, lane = tid & 31, wid = tid >> 5;
    int wm = wid >> 1, wn = wid & 1;              // 2x2 warp grid, 32x32 tiles
    int by = blockIdx.x;                          // n-quarter (0..3)
    int bx = blockIdx.y;
    int mt = bx >> 1, rhalf = bx & 1;             // 128-row blob, 64-row half
    int t = 0;
    while (t < NTYPES - 1 && mt >= p.tileOff[t + 1]) t++;
    int m0 = (mt - p.tileOff[t]) * 128 + rhalf * 64;
    int Mt = p.M[t];

    uint32_t sbraw = smem_u32(dsm);
    uint32_t s0 = (sbraw + 1023u) & ~1023u;
    char* alp = dsm + (s0 - sbraw);
    const uint32_t RINGOFF = (uint32_t)(CHUNKS * 16384);

    // W3 columns owned by this thread (MODE 2 only)
    float w3r[4][2][3];
    if (MODE == 2) {
        #pragma unroll
        for (int nf = 0; nf < 4; nf++) {
            int nc = by * 64 + wn * 32 + nf * 8 + 2 * (lane & 3);
            #pragma unroll
            for (int u = 0; u < 2; u++)
                #pragma unroll
                for (int j = 0; j < 3; j++)
                    w3r[nf][u][j] = W3[(size_t)t * (HID * 3) + (nc + u) * 3 + j];
        }
    }

    float acc[2][4][4];
    if (MODE == 1) {
        // accumulator init = per-garment bias (garf @ W1[128:192])
        #pragma unroll
        for (int mf = 0; mf < 2; mf++) {
            int r0 = m0 + wm * 32 + mf * 16 + (lane >> 2);
            int r1 = r0 + 8;
            int v0 = p.idx[t][min(r0, Mt - 1)];
            int v1 = p.idx[t][min(r1, Mt - 1)];
            int g0 = gov[v0], g1 = gov[v1];
            #pragma unroll
            for (int nf = 0; nf < 4; nf++) {
                int nl = by * 64 + wn * 32 + nf * 8 + 2 * (lane & 3);
                acc[mf][nf][0] = g_bias[g0 * HID + nl];
                acc[mf][nf][1] = g_bias[g0 * HID + nl + 1];
                acc[mf][nf][2] = g_bias[g1 * HID + nl];
                acc[mf][nf][3] = g_bias[g1 * HID + nl + 1];
            }
        }
    } else {
        #pragma unroll
        for (int i = 0; i < 2; i++)
            #pragma unroll
            for (int j = 0; j < 4; j++)
                #pragma unroll
                for (int k = 0; k < 4; k++) acc[i][j][k] = 0.0f;
    }

    // per-lane ldmatrix addressing (SW128: xor (row&7)*16 within the 128B row)
    int aRow = lane & 15;
    int aKext = (lane >> 4) * 16;
    int bRow = ((lane >> 4) << 3) + (lane & 7);
    int bKext = ((lane >> 3) & 1) * 16;
    uint32_t xr = (uint32_t)((lane & 7) * 16);
    uint32_t aBase[2], bBase[2];
    #pragma unroll
    for (int mf = 0; mf < 2; mf++) aBase[mf] = (uint32_t)((wm * 32 + mf * 16 + aRow) * 128);
    #pragma unroll
    for (int n2 = 0; n2 < 2; n2++) bBase[n2] = (uint32_t)((wn * 32 + n2 * 16 + bRow) * 128);

    // A blob sources
    const uint4* Ahg;
    const uint4* Alg;
    size_t astride;
    {
        size_t aoff = (size_t)rhalf * 512;
        if (MODE == 1) {
            Ahg = g_fa_hi + (size_t)(mt * 2) * 1024 + aoff;
            Alg = g_fa_lo + (size_t)(mt * 2) * 1024 + aoff;
        } else {
            Ahg = g_h1_hi + (size_t)(mt * 4) * 1024 + aoff;
            Alg = g_h1_lo + (size_t)(mt * 4) * 1024 + aoff;
        }
        astride = 1024;
    }

    auto issue_A = [&](int c) {
        uint32_t bb = s0 + RINGOFF + (uint32_t)((c & 1) * 16384);
        const uint4* Ah = Ahg + astride * c;
        const uint4* Al = Alg + astride * c;
        #pragma unroll
        for (int i = tid; i < 512; i += 128) {
            cpa16(bb + i * 16,        Ah + i);
            cpa16(bb + 8192 + i * 16, Al + i);
        }
    };

    // Prologue: ALL B chunks (quarter slices) + A0, one commit group.
    {
        const uint4* Bh0 = ((MODE == 1) ? g_B1_hi : g_B2_hi) + (size_t)(t * CHUNKS) * 2048 + (size_t)by * 512;
        const uint4* Bl0 = ((MODE == 1) ? g_B1_lo : g_B2_lo) + (size_t)(t * CHUNKS) * 2048 + (size_t)by * 512;
        #pragma unroll
        for (int c = 0; c < CHUNKS; c++) {
            uint32_t sB = s0 + (uint32_t)(c * 16384);
            const uint4* Bh = Bh0 + (size_t)c * 2048;
            const uint4* Bl = Bl0 + (size_t)c * 2048;
            #pragma unroll
            for (int i = tid; i < 512; i += 128) {
                cpa16(sB + i * 16,        Bh + i);
                cpa16(sB + 8192 + i * 16, Bl + i);
            }
        }
        issue_A(0);
        CP_COMMIT();
    }

    for (int c = 0; c < CHUNKS; c++) {
        __syncthreads();                       // all warps done with chunk c-1
        if (c + 1 < CHUNKS) {
            issue_A(c + 1);                    // slot (c+1)&1, freed by sync above
            CP_COMMIT();
            CP_WAIT1();                        // group c complete
        } else {
            CP_WAIT0();
        }
        __syncthreads();

        uint32_t sAh = s0 + RINGOFF + (uint32_t)((c & 1) * 16384);
        uint32_t sAl = sAh + 8192;
        uint32_t sBh = s0 + (uint32_t)(c * 16384);
        uint32_t sBl = sBh + 8192;

        #pragma unroll
        for (int k16 = 0; k16 < 4; k16++) {
            uint32_t kb = (uint32_t)(k16 * 32);
            uint32_t ah[2][4], al_[2][4], bh[2][4], bl[2][4];
            #pragma unroll
            for (int mf = 0; mf < 2; mf++) {
                uint32_t ka = (kb + (uint32_t)aKext) ^ xr;
                ldm_x4(ah[mf],  sAh + aBase[mf] + ka);
                ldm_x4(al_[mf], sAl + aBase[mf] + ka);
            }
            #pragma unroll
            for (int n2 = 0; n2 < 2; n2++) {
                uint32_t kbx = (kb + (uint32_t)bKext) ^ xr;
                ldm_x4(bh[n2], sBh + bBase[n2] + kbx);
                ldm_x4(bl[n2], sBl + bBase[n2] + kbx);
            }
            // pass 0: a_hi * b_hi
            #pragma unroll
            for (int mf = 0; mf < 2; mf++)
                #pragma unroll
                for (int nf = 0; nf < 4; nf++)
                    mma16816(acc[mf][nf], ah[mf], bh[nf >> 1][(nf & 1) * 2], bh[nf >> 1][(nf & 1) * 2 + 1]);
            // pass 1: a_lo * b_hi
            #pragma unroll
            for (int mf = 0; mf < 2; mf++)
                #pragma unroll
                for (int nf = 0; nf < 4; nf++)
                    mma16816(acc[mf][nf], al_[mf], bh[nf >> 1][(nf & 1) * 2], bh[nf >> 1][(nf & 1) * 2 + 1]);
            // pass 2: a_hi * b_lo
            #pragma unroll
            for (int mf = 0; mf < 2; mf++)
                #pragma unroll
                for (int nf = 0; nf < 4; nf++)
                    mma16816(acc[mf][nf], ah[mf], bl[nf >> 1][(nf & 1) * 2], bl[nf >> 1][(nf & 1) * 2 + 1]);
        }
    }

    if (MODE == 1) {
        // relu + bf16 split, staged through smem ring slot 0 (hi @+0, lo @+8192).
        // Last compute used slot (CHUNKS-1)&1 = 1, so slot 0 is free to write.
        uint32_t hbase = s0 + RINGOFF;
        uint32_t lbase = hbase + 8192;
        #pragma unroll
        for (int mf = 0; mf < 2; mf++) {
            #pragma unroll
            for (int nf = 0; nf < 4; nf++) {
                int R0 = wm * 32 + mf * 16 + (lane >> 2);
                int ncl = wn * 32 + nf * 8 + 2 * (lane & 3);   // 0..63 within quarter
                float c0 = fmaxf(acc[mf][nf][0], 0.0f);
                float c1 = fmaxf(acc[mf][nf][1], 0.0f);
                float c2 = fmaxf(acc[mf][nf][2], 0.0f);
                float c3 = fmaxf(acc[mf][nf][3], 0.0f);
                uint16_t h0, l0, h1, l1, h2, l2, h3, l3;
                bsplit(c0, h0, l0); bsplit(c1, h1, l1);
                bsplit(c2, h2, l2); bsplit(c3, h3, l3);
                uint32_t off0 = SW128((uint32_t)(R0 * 128 + ncl * 2));
                uint32_t off1 = SW128((uint32_t)((R0 + 8) * 128 + ncl * 2));
                sts32(hbase + off0, pk16(h0, h1));
                sts32(hbase + off1, pk16(h2, h3));
                sts32(lbase + off0, pk16(l0, l1));
                sts32(lbase + off1, pk16(l2, l3));
            }
        }
        __syncthreads();
        const uint4* sh = (const uint4*)(alp + RINGOFF);
        const uint4* sl = (const uint4*)(alp + RINGOFF + 8192);
        size_t bbase = (size_t)(mt * 4 + by) * 1024 + (size_t)rhalf * 512;
        #pragma unroll
        for (int i = tid; i < 512; i += 128) {
            g_h1_hi[bbase + i] = sh[i];
            g_h1_lo[bbase + i] = sl[i];
        }
    } else {
        // relu + fused layer-3 dot (64-col partial) + atomic scatter (out pre-zeroed)
        #pragma unroll
        for (int mf = 0; mf < 2; mf++) {
            float s0v[3] = {0.f, 0.f, 0.f}, s1v[3] = {0.f, 0.f, 0.f};
            #pragma unroll
            for (int nf = 0; nf < 4; nf++) {
                float h0 = fmaxf(acc[mf][nf][0], 0.0f);
                float h1 = fmaxf(acc[mf][nf][1], 0.0f);
                float h2 = fmaxf(acc[mf][nf][2], 0.0f);
                float h3 = fmaxf(acc[mf][nf][3], 0.0f);
                #pragma unroll
                for (int j = 0; j < 3; j++) {
                    s0v[j] += h0 * w3r[nf][0][j] + h1 * w3r[nf][1][j];
                    s1v[j] += h2 * w3r[nf][0][j] + h3 * w3r[nf][1][j];
                }
            }
            #pragma unroll
            for (int j = 0; j < 3; j++) {
                #pragma unroll
                for (int off = 1; off <= 2; off <<= 1) {
                    s0v[j] += __shfl_xor_sync(0xFFFFFFFFu, s0v[j], off);
                    s1v[j] += __shfl_xor_sync(0xFFFFFFFFu, s1v[j], off);
                }
            }
            if ((lane & 3) == 0) {
                int R0 = wm * 32 + mf * 16 + (lane >> 2);
                int g0 = m0 + R0, g1 = g0 + 8;
                if (g0 < Mt) {
                    int v = p.idx[t][g0];
                    #pragma unroll
                    for (int j = 0; j < 3; j++) atomicAdd(&out[(size_t)v * 3 + j], s0v[j]);
                }
                if (g1 < Mt) {
                    int v = p.idx[t][g1];
                    #pragma unroll
                    for (int j = 0; j < 3; j++) atomicAdd(&out[(size_t)v * 3 + j], s1v[j]);
                }
            }
        }
    }
}

// ---------------------------------------------------------------------------
// Launch
// ---------------------------------------------------------------------------
#define GEMM1_SMEM (2 * 16384 + 2 * 16384 + 1024)   // 66560
#define GEMM2_SMEM (4 * 16384 + 2 * 16384 + 1024)   // 99328

extern "C" void kernel_launch(void* const* d_in, const int* in_sizes, int n_in,
                              void* d_out, int out_size) {
    const float* imgs     = (const float*)d_in[0];
    const float* pros     = (const float*)d_in[1];
    const float* x_verts  = (const float*)d_in[2];
    const float* W1       = (const float*)d_in[3];
    const float* W2       = (const float*)d_in[4];
    const float* W3       = (const float*)d_in[5];
    const int*   imgbatch = (const int*)d_in[6];
    const int*   gov      = (const int*)d_in[7];
    float*       out      = (float*)d_out;

    P p;
    p.rowOff[0] = 0;
    p.tileOff[0] = 0;
    for (int t = 0; t < NTYPES; t++) {
        p.idx[t] = (const int*)d_in[8 + t];
        p.M[t] = in_sizes[8 + t];
        p.rowOff[t + 1] = p.rowOff[t] + p.M[t];
        p.tileOff[t + 1] = p.tileOff[t] + (p.M[t] + 127) / 128;
    }
    int tiles = p.tileOff[NTYPES];

    cudaFuncSetAttribute(gemm_mma_kernel<2, 1>, cudaFuncAttributeMaxDynamicSharedMemorySize, GEMM1_SMEM);
    cudaFuncSetAttribute(gemm_mma_kernel<4, 2>, cudaFuncAttributeMaxDynamicSharedMemorySize, GEMM2_SMEM);

    // zero the output (layer-3 scatter accumulates with atomics)
    cudaMemsetAsync(d_out, 0, (size_t)out_size * sizeof(float), 0);

    dim3 gG(GARM, CCH);
    roi_garf_kernel<<<gG, 256>>>(imgs, pros, imgbatch);

    dim3 gW(6, 6);
    wimg_kernel<<<gW, 256>>>(W1, W2);

    featimg_kernel<<<tiles, 128>>>(x_verts, p);

    dim3 gB(6, 4);
    bias_kernel<<<gB, 512>>>(W1, gov, p);

    dim3 gM(4, 2 * tiles);
    gemm_mma_kernel<2, 1><<<gM, 128, GEMM1_SMEM>>>(W3, gov, out, p);
    gemm_mma_kernel<4, 2><<<gM, 128, GEMM2_SMEM>>>(W3, gov, out, p);
}

// round 8
// speedup vs baseline: 1.2288x; 1.2288x over previous
#include <cuda_runtime.h>
#include <cuda_fp16.h>
#include <cstdint>
#include <cstddef>

// ---------------------------------------------------------------------------
// Problem constants
// ---------------------------------------------------------------------------
#define NTYPES 6
#define HID    256
#define DV     128
#define CCH    64
#define IMH    192
#define IMW    192
#define GARM   24
#define MAXTILES 816   // sum ceil(M_t/128) <= 809; pad a little

// ---------------------------------------------------------------------------
// Static device scratch. Numerics: A operands = fp16 hi/lo pair (exact to
// 2^-22), B operands = single fp16 (error 1.4e-4 RMS -> final ~2e-4, under
// the 1e-3 threshold with margin). GEMM = 2-pass: a_hi*b + a_lo*b.
//  A tile image: 128 rows x 64 fp16 (128B/row), SW128-swizzled -> 16KB = 1024 uint4
//  B tile image: 256 rows (n) x 64 fp16 (k)  -> 32KB = 2048 uint4   (B^T layout)
// ---------------------------------------------------------------------------
__device__ float g_garf[GARM * CCH];
__device__ float g_bias[GARM * HID];                       // garf @ W1[128:192] (fp32 exact)
__device__ uint4 g_fa_hi[(size_t)MAXTILES * 2 * 1024];     // x_verts only (K=128)
__device__ uint4 g_fa_lo[(size_t)MAXTILES * 2 * 1024];
__device__ uint4 g_h1_hi[(size_t)MAXTILES * 4 * 1024];
__device__ uint4 g_h1_lo[(size_t)MAXTILES * 4 * 1024];
__device__ uint4 g_B1[6 * 2 * 2048];                       // W1[:128], single fp16
__device__ uint4 g_B2[6 * 4 * 2048];                       // W2, single fp16

struct P {
    const int* idx[NTYPES];
    int M[NTYPES];
    int rowOff[NTYPES + 1];
    int tileOff[NTYPES + 1];   // cumsum of ceil(M/128)
};

// ---------------------------------------------------------------------------
// Helpers (base-arch PTX only: ldmatrix / mma.sync / cp.async — all sm_80+)
// ---------------------------------------------------------------------------
__device__ __forceinline__ uint32_t smem_u32(const void* p) {
    uint32_t a;
    asm("{ .reg .u64 t; cvta.to.shared.u64 t, %1; cvt.u32.u64 %0, t; }" : "=r"(a) : "l"(p));
    return a;
}
#define SW128(x) ((x) ^ (((x) >> 3) & 0x70))

__device__ __forceinline__ void cpa16(uint32_t s, const void* g) {
    asm volatile("cp.async.cg.shared.global [%0], [%1], 16;" :: "r"(s), "l"(g));
}
#define CP_COMMIT() asm volatile("cp.async.commit_group;" ::: "memory")
#define CP_WAIT0()  asm volatile("cp.async.wait_group 0;" ::: "memory")
#define CP_WAIT1()  asm volatile("cp.async.wait_group 1;" ::: "memory")

__device__ __forceinline__ void ldm_x4(uint32_t* r, uint32_t addr) {
    asm volatile("ldmatrix.sync.aligned.m8n8.x4.shared.b16 {%0,%1,%2,%3}, [%4];"
                 : "=r"(r[0]), "=r"(r[1]), "=r"(r[2]), "=r"(r[3]) : "r"(addr));
}
// fp16 MMA, fp32 accumulate
__device__ __forceinline__ void mma16816(float* d, const uint32_t* a, uint32_t b0, uint32_t b1) {
    asm volatile(
        "mma.sync.aligned.m16n8k16.row.col.f32.f16.f16.f32 "
        "{%0,%1,%2,%3},{%4,%5,%6,%7},{%8,%9},{%0,%1,%2,%3};"
        : "+f"(d[0]), "+f"(d[1]), "+f"(d[2]), "+f"(d[3])
        : "r"(a[0]), "r"(a[1]), "r"(a[2]), "r"(a[3]), "r"(b0), "r"(b1));
}
__device__ __forceinline__ void sts32(uint32_t addr, uint32_t v) {
    asm volatile("st.shared.b32 [%0], %1;" :: "r"(addr), "r"(v) : "memory");
}

// fp16 hi/lo split + pack
__device__ __forceinline__ void fsplit(float x, uint16_t& h, uint16_t& l) {
    __half hh = __float2half_rn(x);
    float hf = __half2float(hh);
    __half ll = __float2half_rn(x - hf);
    h = *reinterpret_cast<uint16_t*>(&hh);
    l = *reinterpret_cast<uint16_t*>(&ll);
}
__device__ __forceinline__ uint16_t f2h(float x) {
    __half hh = __float2half_rn(x);
    return *reinterpret_cast<uint16_t*>(&hh);
}
__device__ __forceinline__ uint32_t pk16(uint16_t a, uint16_t b) {
    return (uint32_t)a | ((uint32_t)b << 16);
}
// split 8 floats -> hi uint4 + lo uint4 (fp16)
__device__ __forceinline__ void split8(const float* v, uint4& hq, uint4& lq) {
    uint16_t h[8], l[8];
    #pragma unroll
    for (int i = 0; i < 8; i++) fsplit(v[i], h[i], l[i]);
    hq = make_uint4(pk16(h[0], h[1]), pk16(h[2], h[3]), pk16(h[4], h[5]), pk16(h[6], h[7]));
    lq = make_uint4(pk16(l[0], l[1]), pk16(l[2], l[3]), pk16(l[4], l[5]), pk16(l[6], l[7]));
}
// pack 8 floats -> single fp16 uint4
__device__ __forceinline__ uint4 pack8(const float* v) {
    return make_uint4(pk16(f2h(v[0]), f2h(v[1])), pk16(f2h(v[2]), f2h(v[3])),
                      pk16(f2h(v[4]), f2h(v[5])), pk16(f2h(v[6]), f2h(v[7])));
}

// ---------------------------------------------------------------------------
// Kernel 1: ROI-align + mean pool -> g_garf
// ---------------------------------------------------------------------------
__global__ void roi_garf_kernel(const float* __restrict__ imgs,
                                const float* __restrict__ pros,
                                const int* __restrict__ imgbatch) {
    int g = blockIdx.x, c = blockIdx.y, tid = threadIdx.x;
    int b = imgbatch[g];
    float px = pros[2 * g + 0], py = pros[2 * g + 1];
    const float* im = imgs + ((size_t)(b * CCH + c)) * (IMH * IMW);
    float sum = 0.0f;
    #pragma unroll
    for (int s = tid; s < 1024; s += 256) {
        int i = s >> 5, j = s & 31;
        float y = py - 16.0f + (float)i + 0.5f;
        float x = px - 16.0f + (float)j + 0.5f;
        float yf = floorf(y), xf = floorf(x);
        float wy = y - yf, wx = x - xf;
        int y0 = (int)yf, x0 = (int)xf, y1, x1;
        y1 = min(max(y0 + 1, 0), IMH - 1); x1 = min(max(x0 + 1, 0), IMW - 1);
        y0 = min(max(y0, 0), IMH - 1);     x0 = min(max(x0, 0), IMW - 1);
        float v00 = im[y0 * IMW + x0], v01 = im[y0 * IMW + x1];
        float v10 = im[y1 * IMW + x0], v11 = im[y1 * IMW + x1];
        sum += (1.0f - wy) * ((1.0f - wx) * v00 + wx * v01)
             +          wy * ((1.0f - wx) * v10 + wx * v11);
    }
    __shared__ float red[256];
    red[tid] = sum;
    __syncthreads();
    #pragma unroll
    for (int off = 128; off > 0; off >>= 1) {
        if (tid < off) red[tid] += red[tid + off];
        __syncthreads();
    }
    if (tid == 0) g_garf[g * CCH + c] = red[0] * (1.0f / 1024.0f);
}

// ---------------------------------------------------------------------------
// Kernel 1b: per-garment layer-1 bias: bias[g] = garf[g] @ W1[t(g)][128:192].
// grid (6, 4), 512 threads: n = tid&255 (output col), kh = tid>>8 (k half).
// ---------------------------------------------------------------------------
__global__ void bias_kernel(const float* __restrict__ W1,
                            const int* __restrict__ gov, P p) {
    int t = blockIdx.x, j = blockIdx.y, tid = threadIdx.x;
    int n = tid & 255, kh = tid >> 8;
    int g = gov[p.idx[t][j * (p.M[t] >> 2)]];
    __shared__ float gf[CCH];
    __shared__ float part[512];
    if (tid < CCH) gf[tid] = g_garf[g * CCH + tid];
    __syncthreads();
    const float* w = W1 + ((size_t)t * 192 + DV + kh * 32) * HID + n;
    float s = 0.0f;
    #pragma unroll 8
    for (int k = 0; k < 32; k++) s += gf[kh * 32 + k] * w[(size_t)k * HID];
    part[tid] = s;
    __syncthreads();
    if (kh == 0) g_bias[g * HID + n] = part[n] + part[n + 256];
}

// ---------------------------------------------------------------------------
// Kernel 2: weight images (single fp16). grid (6, 6): y<2 layer1, else layer2.
// ---------------------------------------------------------------------------
__global__ void wimg_kernel(const float* __restrict__ W1, const float* __restrict__ W2) {
    int t = blockIdx.x, cc = blockIdx.y, n = threadIdx.x;
    const float* W;
    uint4* d;
    int c;
    if (cc < 2) {
        c = cc;
        W = W1 + (size_t)t * 192 * 256;
        d = g_B1 + (size_t)(t * 2 + c) * 2048;
    } else {
        c = cc - 2;
        W = W2 + (size_t)t * 256 * 256;
        d = g_B2 + (size_t)(t * 4 + c) * 2048;
    }
    #pragma unroll
    for (int g4 = 0; g4 < 8; g4++) {
        float v[8];
        #pragma unroll
        for (int i = 0; i < 8; i++) v[i] = W[(size_t)(c * 64 + g4 * 8 + i) * 256 + n];
        uint32_t sw = SW128((uint32_t)(n * 128 + g4 * 16));
        d[sw >> 4] = pack8(v);
    }
}

// ---------------------------------------------------------------------------
// Kernel 3: feature images (x_verts only, fp16 hi/lo). grid = tiles, 128 thr.
// ---------------------------------------------------------------------------
__global__ void featimg_kernel(const float* __restrict__ xv, P p) {
    int mt = blockIdx.x, r = threadIdx.x;
    int t = 0;
    while (t < NTYPES - 1 && mt >= p.tileOff[t + 1]) t++;
    int grow = (mt - p.tileOff[t]) * 128 + r;
    bool valid = grow < p.M[t];
    int v = valid ? p.idx[t][grow] : 0;
    #pragma unroll
    for (int c = 0; c < 2; c++) {
        const float* src = xv + (size_t)v * DV + c * 64;
        uint4* dh = g_fa_hi + (size_t)(mt * 2 + c) * 1024;
        uint4* dl = g_fa_lo + (size_t)(mt * 2 + c) * 1024;
        #pragma unroll
        for (int g4 = 0; g4 < 8; g4++) {
            float v8[8];
            if (valid) {
                float4 f0 = *(const float4*)(src + g4 * 8);
                float4 f1 = *(const float4*)(src + g4 * 8 + 4);
                v8[0] = f0.x; v8[1] = f0.y; v8[2] = f0.z; v8[3] = f0.w;
                v8[4] = f1.x; v8[5] = f1.y; v8[6] = f1.z; v8[7] = f1.w;
            } else {
                #pragma unroll
                for (int i = 0; i < 8; i++) v8[i] = 0.0f;
            }
            uint4 hq, lq;
            split8(v8, hq, lq);
            uint32_t sw = SW128((uint32_t)(r * 128 + g4 * 16));
            dh[sw >> 4] = hq;
            dl[sw >> 4] = lq;
        }
    }
}

// ---------------------------------------------------------------------------
// Kernel 4/5: double-buffered mma.sync fp16 GEMM, 2-pass, 2 CTAs/SM.
// CTA = 64x128 output tile, 256 threads, 8 warps (2x4 grid of 32x32 tiles).
// grid = (2*tiles m-halves [fastest], 2 n-halves).
// Stage = A(8+8KB hi/lo) + B(16KB single) = 32KB; 2 stages = 64KB.
// MODE 1: A = feat blobs (2 chunks, K=128), acc init = per-garment bias,
//         epilogue relu+split -> h1 blobs.
// MODE 2: A = h1 blobs (4 chunks), epilogue relu + fused layer3 + atomic scatter.
// ---------------------------------------------------------------------------
#define STAGE_BYTES 32768

template <int CHUNKS, int MODE>
__global__ __launch_bounds__(256, 2)
void gemm_mma_kernel(const float* __restrict__ W3,
                     const int* __restrict__ gov,
                     float* __restrict__ out, P p) {
    extern __shared__ char dsm[];
    int tid = threadIdx.x, lane = tid & 31, wid = tid >> 5;
    int wm = wid >> 2, wn = wid & 3;              // 2x4 warp grid, 32x32 tiles
    int bx = blockIdx.x, by = blockIdx.y;
    int mt = bx >> 1, rhalf = bx & 1;             // 128-row blob, 64-row half
    int t = 0;
    while (t < NTYPES - 1 && mt >= p.tileOff[t + 1]) t++;
    int m0 = (mt - p.tileOff[t]) * 128 + rhalf * 64;
    int Mt = p.M[t];

    uint32_t sbraw = smem_u32(dsm);
    uint32_t s0 = (sbraw + 1023u) & ~1023u;
    char* alp = dsm + (s0 - sbraw);

    // W3 columns owned by this thread (MODE 2 only)
    float w3r[4][2][3];
    if (MODE == 2) {
        #pragma unroll
        for (int nf = 0; nf < 4; nf++) {
            int nc = by * 128 + wn * 32 + nf * 8 + 2 * (lane & 3);
            #pragma unroll
            for (int u = 0; u < 2; u++)
                #pragma unroll
                for (int j = 0; j < 3; j++)
                    w3r[nf][u][j] = W3[(size_t)t * (HID * 3) + (nc + u) * 3 + j];
        }
    }

    float acc[2][4][4];
    if (MODE == 1) {
        // accumulator init = per-garment bias (garf @ W1[128:192], fp32 exact)
        #pragma unroll
        for (int mf = 0; mf < 2; mf++) {
            int r0 = m0 + wm * 32 + mf * 16 + (lane >> 2);
            int r1 = r0 + 8;
            int v0 = p.idx[t][min(r0, Mt - 1)];
            int v1 = p.idx[t][min(r1, Mt - 1)];
            int g0 = gov[v0], g1 = gov[v1];
            #pragma unroll
            for (int nf = 0; nf < 4; nf++) {
                int nl = by * 128 + wn * 32 + nf * 8 + 2 * (lane & 3);
                acc[mf][nf][0] = g_bias[g0 * HID + nl];
                acc[mf][nf][1] = g_bias[g0 * HID + nl + 1];
                acc[mf][nf][2] = g_bias[g1 * HID + nl];
                acc[mf][nf][3] = g_bias[g1 * HID + nl + 1];
            }
        }
    } else {
        #pragma unroll
        for (int i = 0; i < 2; i++)
            #pragma unroll
            for (int j = 0; j < 4; j++)
                #pragma unroll
                for (int k = 0; k < 4; k++) acc[i][j][k] = 0.0f;
    }

    // per-lane ldmatrix addressing (SW128: xor (row&7)*16 within the 128B row)
    int aRow = lane & 15;
    int aKext = (lane >> 4) * 16;
    int bRow = ((lane >> 4) << 3) + (lane & 7);
    int bKext = ((lane >> 3) & 1) * 16;
    uint32_t xr = (uint32_t)((lane & 7) * 16);
    uint32_t aBase[2], bBase[2];
    #pragma unroll
    for (int mf = 0; mf < 2; mf++) aBase[mf] = (uint32_t)((wm * 32 + mf * 16 + aRow) * 128);
    #pragma unroll
    for (int n2 = 0; n2 < 2; n2++) bBase[n2] = (uint32_t)((wn * 32 + n2 * 16 + bRow) * 128);

    // stage layout: Ah @0 (8KB), Al @8192 (8KB), B @16384 (16KB)
    auto issue_stage = [&](int c, int buf) {
        const uint4 *Ah, *Al, *B;
        size_t aoff = (size_t)rhalf * 512;
        if (MODE == 1) {
            Ah = g_fa_hi + (size_t)(mt * 2 + c) * 1024 + aoff;
            Al = g_fa_lo + (size_t)(mt * 2 + c) * 1024 + aoff;
            B  = g_B1 + (size_t)(t * 2 + c) * 2048 + (size_t)by * 1024;
        } else {
            Ah = g_h1_hi + (size_t)(mt * 4 + c) * 1024 + aoff;
            Al = g_h1_lo + (size_t)(mt * 4 + c) * 1024 + aoff;
            B  = g_B2 + (size_t)(t * 4 + c) * 2048 + (size_t)by * 1024;
        }
        uint32_t bb = s0 + buf * STAGE_BYTES;
        #pragma unroll
        for (int i = tid; i < 512; i += 256) {
            cpa16(bb + i * 16,        Ah + i);
            cpa16(bb + 8192 + i * 16, Al + i);
        }
        #pragma unroll
        for (int i = tid; i < 1024; i += 256) {
            cpa16(bb + 16384 + i * 16, B + i);
        }
        CP_COMMIT();
    };

    issue_stage(0, 0);

    for (int c = 0; c < CHUNKS; c++) {
        if (c + 1 < CHUNKS) {
            issue_stage(c + 1, (c + 1) & 1);
            CP_WAIT1();
        } else {
            CP_WAIT0();
        }
        __syncthreads();

        uint32_t bb = s0 + (c & 1) * STAGE_BYTES;
        uint32_t sAh = bb, sAl = bb + 8192, sB = bb + 16384;

        #pragma unroll
        for (int k16 = 0; k16 < 4; k16++) {
            uint32_t kb = (uint32_t)(k16 * 32);
            uint32_t ah[2][4], al_[2][4], bfr[2][4];
            #pragma unroll
            for (int mf = 0; mf < 2; mf++) {
                uint32_t ka = (kb + (uint32_t)aKext) ^ xr;
                ldm_x4(ah[mf],  sAh + aBase[mf] + ka);
                ldm_x4(al_[mf], sAl + aBase[mf] + ka);
            }
            #pragma unroll
            for (int n2 = 0; n2 < 2; n2++) {
                uint32_t kbx = (kb + (uint32_t)bKext) ^ xr;
                ldm_x4(bfr[n2], sB + bBase[n2] + kbx);
            }
            // pass 0: a_hi * b
            #pragma unroll
            for (int mf = 0; mf < 2; mf++)
                #pragma unroll
                for (int nf = 0; nf < 4; nf++)
                    mma16816(acc[mf][nf], ah[mf], bfr[nf >> 1][(nf & 1) * 2], bfr[nf >> 1][(nf & 1) * 2 + 1]);
            // pass 1: a_lo * b
            #pragma unroll
            for (int mf = 0; mf < 2; mf++)
                #pragma unroll
                for (int nf = 0; nf < 4; nf++)
                    mma16816(acc[mf][nf], al_[mf], bfr[nf >> 1][(nf & 1) * 2], bfr[nf >> 1][(nf & 1) * 2 + 1]);
        }
        __syncthreads();
    }

    if (MODE == 1) {
        // relu + fp16 split, staged through smem (reuse stage0):
        //   hi: s0 + loc*8192 (64 rows x 128B), lo: s0 + 16384 + loc*8192
        #pragma unroll
        for (int mf = 0; mf < 2; mf++) {
            #pragma unroll
            for (int nf = 0; nf < 4; nf++) {
                int R0 = wm * 32 + mf * 16 + (lane >> 2);
                int nl = wn * 32 + nf * 8 + 2 * (lane & 3);
                int loc = nl >> 6, ncl = nl & 63;
                float c0 = fmaxf(acc[mf][nf][0], 0.0f);
                float c1 = fmaxf(acc[mf][nf][1], 0.0f);
                float c2 = fmaxf(acc[mf][nf][2], 0.0f);
                float c3 = fmaxf(acc[mf][nf][3], 0.0f);
                uint16_t h0, l0, h1, l1, h2, l2, h3, l3;
                fsplit(c0, h0, l0); fsplit(c1, h1, l1);
                fsplit(c2, h2, l2); fsplit(c3, h3, l3);
                uint32_t off0 = SW128((uint32_t)(R0 * 128 + ncl * 2));
                uint32_t off1 = SW128((uint32_t)((R0 + 8) * 128 + ncl * 2));
                uint32_t hbase = s0 + loc * 8192;
                uint32_t lbase = s0 + 16384 + loc * 8192;
                sts32(hbase + off0, pk16(h0, h1));
                sts32(hbase + off1, pk16(h2, h3));
                sts32(lbase + off0, pk16(l0, l1));
                sts32(lbase + off1, pk16(l2, l3));
            }
        }
        __syncthreads();
        const uint4* sh = (const uint4*)alp;
        const uint4* sl = (const uint4*)(alp + 16384);
        #pragma unroll
        for (int i = tid; i < 1024; i += 256) {
            int cg = by * 2 + (i >> 9);
            size_t bidx = (size_t)(mt * 4 + cg) * 1024 + (size_t)rhalf * 512 + (i & 511);
            g_h1_hi[bidx] = sh[i];
            g_h1_lo[bidx] = sl[i];
        }
    } else {
        // relu + fused layer-3 dot + atomic scatter (out pre-zeroed)
        #pragma unroll
        for (int mf = 0; mf < 2; mf++) {
            float s0v[3] = {0.f, 0.f, 0.f}, s1v[3] = {0.f, 0.f, 0.f};
            #pragma unroll
            for (int nf = 0; nf < 4; nf++) {
                float h0 = fmaxf(acc[mf][nf][0], 0.0f);
                float h1 = fmaxf(acc[mf][nf][1], 0.0f);
                float h2 = fmaxf(acc[mf][nf][2], 0.0f);
                float h3 = fmaxf(acc[mf][nf][3], 0.0f);
                #pragma unroll
                for (int j = 0; j < 3; j++) {
                    s0v[j] += h0 * w3r[nf][0][j] + h1 * w3r[nf][1][j];
                    s1v[j] += h2 * w3r[nf][0][j] + h3 * w3r[nf][1][j];
                }
            }
            #pragma unroll
            for (int j = 0; j < 3; j++) {
                #pragma unroll
                for (int off = 1; off <= 2; off <<= 1) {
                    s0v[j] += __shfl_xor_sync(0xFFFFFFFFu, s0v[j], off);
                    s1v[j] += __shfl_xor_sync(0xFFFFFFFFu, s1v[j], off);
                }
            }
            if ((lane & 3) == 0) {
                int R0 = wm * 32 + mf * 16 + (lane >> 2);
                int g0 = m0 + R0, g1 = g0 + 8;
                if (g0 < Mt) {
                    int v = p.idx[t][g0];
                    #pragma unroll
                    for (int j = 0; j < 3; j++) atomicAdd(&out[(size_t)v * 3 + j], s0v[j]);
                }
                if (g1 < Mt) {
                    int v = p.idx[t][g1];
                    #pragma unroll
                    for (int j = 0; j < 3; j++) atomicAdd(&out[(size_t)v * 3 + j], s1v[j]);
                }
            }
        }
    }
}

// ---------------------------------------------------------------------------
// Launch
// ---------------------------------------------------------------------------
#define GEMM_SMEM (2 * STAGE_BYTES + 1024)

extern "C" void kernel_launch(void* const* d_in, const int* in_sizes, int n_in,
                              void* d_out, int out_size) {
    const float* imgs     = (const float*)d_in[0];
    const float* pros     = (const float*)d_in[1];
    const float* x_verts  = (const float*)d_in[2];
    const float* W1       = (const float*)d_in[3];
    const float* W2       = (const float*)d_in[4];
    const float* W3       = (const float*)d_in[5];
    const int*   imgbatch = (const int*)d_in[6];
    const int*   gov      = (const int*)d_in[7];
    float*       out      = (float*)d_out;

    P p;
    p.rowOff[0] = 0;
    p.tileOff[0] = 0;
    for (int t = 0; t < NTYPES; t++) {
        p.idx[t] = (const int*)d_in[8 + t];
        p.M[t] = in_sizes[8 + t];
        p.rowOff[t + 1] = p.rowOff[t] + p.M[t];
        p.tileOff[t + 1] = p.tileOff[t] + (p.M[t] + 127) / 128;
    }
    int tiles = p.tileOff[NTYPES];

    cudaFuncSetAttribute(gemm_mma_kernel<2, 1>, cudaFuncAttributeMaxDynamicSharedMemorySize, GEMM_SMEM);
    cudaFuncSetAttribute(gemm_mma_kernel<4, 2>, cudaFuncAttributeMaxDynamicSharedMemorySize, GEMM_SMEM);

    // zero the output (layer-3 scatter accumulates with atomics)
    cudaMemsetAsync(d_out, 0, (size_t)out_size * sizeof(float), 0);

    dim3 gG(GARM, CCH);
    roi_garf_kernel<<<gG, 256>>>(imgs, pros, imgbatch);

    dim3 gW(6, 6);
    wimg_kernel<<<gW, 256>>>(W1, W2);

    featimg_kernel<<<tiles, 128>>>(x_verts, p);

    dim3 gB(6, 4);
    bias_kernel<<<gB, 512>>>(W1, gov, p);

    dim3 gM(2 * tiles, 2);
    gemm_mma_kernel<2, 1><<<gM, 256, GEMM_SMEM>>>(W3, gov, out, p);
    gemm_mma_kernel<4, 2><<<gM, 256, GEMM_SMEM>>>(W3, gov, out, p);
}

// round 9
// speedup vs baseline: 1.7596x; 1.4320x over previous
#include <cuda_runtime.h>
#include <cuda_fp16.h>
#include <cstdint>
#include <cstddef>

// ---------------------------------------------------------------------------
// Problem constants
// ---------------------------------------------------------------------------
#define NTYPES 6
#define HID    256
#define DV     128
#define CCH    64
#define IMH    192
#define IMW    192
#define GARM   24
#define MAXTILES 816   // sum ceil(M_t/128) <= 809; pad a little

// ---------------------------------------------------------------------------
// Numerics: all GEMM operands single fp16 (A and B), fp32 accumulate.
// 4 fp16 rounding sources (xv, W1, h1, W2) ~2e-4 RMS each -> ~4e-4 total,
// under the 1e-3 threshold with ~2.4x margin. Garment image term via fp32
// bias (exact). Layer 3 fully fp32.
//  A chunk image: 128 rows x 64 fp16 (128B/row), SW128 -> 16KB = 1024 uint4
//  B chunk image: 256 rows (n) x 64 fp16 (k)      SW128 -> 32KB = 2048 uint4
// ---------------------------------------------------------------------------
__device__ float g_garf[GARM * CCH];
__device__ float g_bias[GARM * HID];                   // garf @ W1[128:192] (fp32)
__device__ uint4 g_fa[(size_t)MAXTILES * 2 * 1024];    // x_verts fp16 (K=128)
__device__ uint4 g_h1[(size_t)MAXTILES * 4 * 1024];    // relu(h1) fp16 (K=256)
__device__ uint4 g_B1[6 * 2 * 2048];                   // W1[:128] fp16
__device__ uint4 g_B2[6 * 4 * 2048];                   // W2 fp16

struct P {
    const int* idx[NTYPES];
    int M[NTYPES];
    int rowOff[NTYPES + 1];
    int tileOff[NTYPES + 1];   // cumsum of ceil(M/128)
};

// ---------------------------------------------------------------------------
// Helpers (base-arch PTX only: ldmatrix / mma.sync / cp.async — all sm_80+)
// ---------------------------------------------------------------------------
__device__ __forceinline__ uint32_t smem_u32(const void* p) {
    uint32_t a;
    asm("{ .reg .u64 t; cvta.to.shared.u64 t, %1; cvt.u32.u64 %0, t; }" : "=r"(a) : "l"(p));
    return a;
}
#define SW128(x) ((x) ^ (((x) >> 3) & 0x70))

__device__ __forceinline__ void cpa16(uint32_t s, const void* g) {
    asm volatile("cp.async.cg.shared.global [%0], [%1], 16;" :: "r"(s), "l"(g));
}
#define CP_COMMIT() asm volatile("cp.async.commit_group;" ::: "memory")
#define CP_WAIT0()  asm volatile("cp.async.wait_group 0;" ::: "memory")
#define CP_WAIT1()  asm volatile("cp.async.wait_group 1;" ::: "memory")

__device__ __forceinline__ void ldm_x4(uint32_t* r, uint32_t addr) {
    asm volatile("ldmatrix.sync.aligned.m8n8.x4.shared.b16 {%0,%1,%2,%3}, [%4];"
                 : "=r"(r[0]), "=r"(r[1]), "=r"(r[2]), "=r"(r[3]) : "r"(addr));
}
// fp16 MMA, fp32 accumulate
__device__ __forceinline__ void mma16816(float* d, const uint32_t* a, uint32_t b0, uint32_t b1) {
    asm volatile(
        "mma.sync.aligned.m16n8k16.row.col.f32.f16.f16.f32 "
        "{%0,%1,%2,%3},{%4,%5,%6,%7},{%8,%9},{%0,%1,%2,%3};"
        : "+f"(d[0]), "+f"(d[1]), "+f"(d[2]), "+f"(d[3])
        : "r"(a[0]), "r"(a[1]), "r"(a[2]), "r"(a[3]), "r"(b0), "r"(b1));
}
__device__ __forceinline__ void sts32(uint32_t addr, uint32_t v) {
    asm volatile("st.shared.b32 [%0], %1;" :: "r"(addr), "r"(v) : "memory");
}

__device__ __forceinline__ uint16_t f2h(float x) {
    __half hh = __float2half_rn(x);
    return *reinterpret_cast<uint16_t*>(&hh);
}
__device__ __forceinline__ uint32_t pk16(uint16_t a, uint16_t b) {
    return (uint32_t)a | ((uint32_t)b << 16);
}
__device__ __forceinline__ uint4 pack8(const float* v) {
    return make_uint4(pk16(f2h(v[0]), f2h(v[1])), pk16(f2h(v[2]), f2h(v[3])),
                      pk16(f2h(v[4]), f2h(v[5])), pk16(f2h(v[6]), f2h(v[7])));
}

// ---------------------------------------------------------------------------
// Kernel 1: ROI-align + mean pool -> g_garf
// ---------------------------------------------------------------------------
__global__ void roi_garf_kernel(const float* __restrict__ imgs,
                                const float* __restrict__ pros,
                                const int* __restrict__ imgbatch) {
    int g = blockIdx.x, c = blockIdx.y, tid = threadIdx.x;
    int b = imgbatch[g];
    float px = pros[2 * g + 0], py = pros[2 * g + 1];
    const float* im = imgs + ((size_t)(b * CCH + c)) * (IMH * IMW);
    float sum = 0.0f;
    #pragma unroll
    for (int s = tid; s < 1024; s += 256) {
        int i = s >> 5, j = s & 31;
        float y = py - 16.0f + (float)i + 0.5f;
        float x = px - 16.0f + (float)j + 0.5f;
        float yf = floorf(y), xf = floorf(x);
        float wy = y - yf, wx = x - xf;
        int y0 = (int)yf, x0 = (int)xf, y1, x1;
        y1 = min(max(y0 + 1, 0), IMH - 1); x1 = min(max(x0 + 1, 0), IMW - 1);
        y0 = min(max(y0, 0), IMH - 1);     x0 = min(max(x0, 0), IMW - 1);
        float v00 = im[y0 * IMW + x0], v01 = im[y0 * IMW + x1];
        float v10 = im[y1 * IMW + x0], v11 = im[y1 * IMW + x1];
        sum += (1.0f - wy) * ((1.0f - wx) * v00 + wx * v01)
             +          wy * ((1.0f - wx) * v10 + wx * v11);
    }
    __shared__ float red[256];
    red[tid] = sum;
    __syncthreads();
    #pragma unroll
    for (int off = 128; off > 0; off >>= 1) {
        if (tid < off) red[tid] += red[tid + off];
        __syncthreads();
    }
    if (tid == 0) g_garf[g * CCH + c] = red[0] * (1.0f / 1024.0f);
}

// ---------------------------------------------------------------------------
// Kernel 2 (merged prep): block-range dispatch, 256 threads.
//   [0, tiles)            : feature images (x_verts -> fp16 blobs)
//   [tiles, tiles+36)     : weight images (fp16)
//   [tiles+36, tiles+60)  : per-garment bias (garf @ W1[128:192], fp32)
// ---------------------------------------------------------------------------
__global__ void prep_kernel(const float* __restrict__ xv,
                            const float* __restrict__ W1,
                            const float* __restrict__ W2,
                            const int* __restrict__ gov,
                            P p, int tiles) {
    int blk = blockIdx.x, tid = threadIdx.x;
    if (blk < tiles) {
        // --- feature image: tile blk, thread = (chunk c, row r) ---
        int mt = blk;
        int r = tid & 127, c = tid >> 7;
        int t = 0;
        while (t < NTYPES - 1 && mt >= p.tileOff[t + 1]) t++;
        int grow = (mt - p.tileOff[t]) * 128 + r;
        bool valid = grow < p.M[t];
        int v = valid ? p.idx[t][grow] : 0;
        const float* src = xv + (size_t)v * DV + c * 64;
        uint4* d = g_fa + (size_t)(mt * 2 + c) * 1024;
        #pragma unroll
        for (int g4 = 0; g4 < 8; g4++) {
            float v8[8];
            if (valid) {
                float4 f0 = *(const float4*)(src + g4 * 8);
                float4 f1 = *(const float4*)(src + g4 * 8 + 4);
                v8[0] = f0.x; v8[1] = f0.y; v8[2] = f0.z; v8[3] = f0.w;
                v8[4] = f1.x; v8[5] = f1.y; v8[6] = f1.z; v8[7] = f1.w;
            } else {
                #pragma unroll
                for (int i = 0; i < 8; i++) v8[i] = 0.0f;
            }
            uint32_t sw = SW128((uint32_t)(r * 128 + g4 * 16));
            d[sw >> 4] = pack8(v8);
        }
    } else if (blk < tiles + 36) {
        // --- weight image ---
        int bb = blk - tiles;
        int t = bb / 6, cc = bb % 6, n = tid;
        const float* W;
        uint4* d;
        int c;
        if (cc < 2) {
            c = cc;
            W = W1 + (size_t)t * 192 * 256;
            d = g_B1 + (size_t)(t * 2 + c) * 2048;
        } else {
            c = cc - 2;
            W = W2 + (size_t)t * 256 * 256;
            d = g_B2 + (size_t)(t * 4 + c) * 2048;
        }
        #pragma unroll
        for (int g4 = 0; g4 < 8; g4++) {
            float v[8];
            #pragma unroll
            for (int i = 0; i < 8; i++) v[i] = W[(size_t)(c * 64 + g4 * 8 + i) * 256 + n];
            uint32_t sw = SW128((uint32_t)(n * 128 + g4 * 16));
            d[sw >> 4] = pack8(v);
        }
    } else {
        // --- per-garment bias (fp32 exact) ---
        int bb = blk - tiles - 36;
        int t = bb >> 2, j = bb & 3;
        int g = gov[p.idx[t][j * (p.M[t] >> 2)]];
        __shared__ float gf[CCH];
        if (tid < CCH) gf[tid] = g_garf[g * CCH + tid];
        __syncthreads();
        const float* w = W1 + ((size_t)t * 192 + DV) * HID + tid;
        float s = 0.0f;
        #pragma unroll 8
        for (int k = 0; k < CCH; k++) s += gf[k] * w[(size_t)k * HID];
        g_bias[g * HID + tid] = s;
    }
}

// ---------------------------------------------------------------------------
// Kernel 3/4: double-buffered mma.sync fp16 GEMM, single-pass, 2 CTAs/SM.
// CTA = 64x128 output tile, 256 threads, 8 warps (2x4 grid of 32x32 tiles).
// grid = (2*tiles m-halves [fastest], 2 n-halves).
// Stage = A(8KB) + B(16KB) = 24KB; 2 stages = 48KB.
// MODE 1: A = feat blobs (2 chunks, K=128), acc init = per-garment bias,
//         epilogue relu -> fp16 h1 blobs.
// MODE 2: A = h1 blobs (4 chunks), epilogue relu + fused layer3 + atomic scatter.
// ---------------------------------------------------------------------------
#define STAGE_BYTES 24576

template <int CHUNKS, int MODE>
__global__ __launch_bounds__(256, 2)
void gemm_mma_kernel(const float* __restrict__ W3,
                     const int* __restrict__ gov,
                     float* __restrict__ out, P p) {
    extern __shared__ char dsm[];
    int tid = threadIdx.x, lane = tid & 31, wid = tid >> 5;
    int wm = wid >> 2, wn = wid & 3;              // 2x4 warp grid, 32x32 tiles
    int bx = blockIdx.x, by = blockIdx.y;
    int mt = bx >> 1, rhalf = bx & 1;             // 128-row blob, 64-row half
    int t = 0;
    while (t < NTYPES - 1 && mt >= p.tileOff[t + 1]) t++;
    int m0 = (mt - p.tileOff[t]) * 128 + rhalf * 64;
    int Mt = p.M[t];

    uint32_t sbraw = smem_u32(dsm);
    uint32_t s0 = (sbraw + 1023u) & ~1023u;
    char* alp = dsm + (s0 - sbraw);

    // W3 columns owned by this thread (MODE 2 only)
    float w3r[4][2][3];
    if (MODE == 2) {
        #pragma unroll
        for (int nf = 0; nf < 4; nf++) {
            int nc = by * 128 + wn * 32 + nf * 8 + 2 * (lane & 3);
            #pragma unroll
            for (int u = 0; u < 2; u++)
                #pragma unroll
                for (int j = 0; j < 3; j++)
                    w3r[nf][u][j] = W3[(size_t)t * (HID * 3) + (nc + u) * 3 + j];
        }
    }

    float acc[2][4][4];
    if (MODE == 1) {
        // accumulator init = per-garment bias (garf @ W1[128:192], fp32 exact)
        #pragma unroll
        for (int mf = 0; mf < 2; mf++) {
            int r0 = m0 + wm * 32 + mf * 16 + (lane >> 2);
            int r1 = r0 + 8;
            int v0 = p.idx[t][min(r0, Mt - 1)];
            int v1 = p.idx[t][min(r1, Mt - 1)];
            int g0 = gov[v0], g1 = gov[v1];
            #pragma unroll
            for (int nf = 0; nf < 4; nf++) {
                int nl = by * 128 + wn * 32 + nf * 8 + 2 * (lane & 3);
                acc[mf][nf][0] = g_bias[g0 * HID + nl];
                acc[mf][nf][1] = g_bias[g0 * HID + nl + 1];
                acc[mf][nf][2] = g_bias[g1 * HID + nl];
                acc[mf][nf][3] = g_bias[g1 * HID + nl + 1];
            }
        }
    } else {
        #pragma unroll
        for (int i = 0; i < 2; i++)
            #pragma unroll
            for (int j = 0; j < 4; j++)
                #pragma unroll
                for (int k = 0; k < 4; k++) acc[i][j][k] = 0.0f;
    }

    // per-lane ldmatrix addressing (SW128: xor (row&7)*16 within the 128B row)
    int aRow = lane & 15;
    int aKext = (lane >> 4) * 16;
    int bRow = ((lane >> 4) << 3) + (lane & 7);
    int bKext = ((lane >> 3) & 1) * 16;
    uint32_t xr = (uint32_t)((lane & 7) * 16);
    uint32_t aBase[2], bBase[2];
    #pragma unroll
    for (int mf = 0; mf < 2; mf++) aBase[mf] = (uint32_t)((wm * 32 + mf * 16 + aRow) * 128);
    #pragma unroll
    for (int n2 = 0; n2 < 2; n2++) bBase[n2] = (uint32_t)((wn * 32 + n2 * 16 + bRow) * 128);

    // stage layout: A @0 (8KB), B @8192 (16KB)
    auto issue_stage = [&](int c, int buf) {
        const uint4 *A, *B;
        size_t aoff = (size_t)rhalf * 512;
        if (MODE == 1) {
            A = g_fa + (size_t)(mt * 2 + c) * 1024 + aoff;
            B = g_B1 + (size_t)(t * 2 + c) * 2048 + (size_t)by * 1024;
        } else {
            A = g_h1 + (size_t)(mt * 4 + c) * 1024 + aoff;
            B = g_B2 + (size_t)(t * 4 + c) * 2048 + (size_t)by * 1024;
        }
        uint32_t bb = s0 + buf * STAGE_BYTES;
        #pragma unroll
        for (int i = tid; i < 512; i += 256) {
            cpa16(bb + i * 16, A + i);
        }
        #pragma unroll
        for (int i = tid; i < 1024; i += 256) {
            cpa16(bb + 8192 + i * 16, B + i);
        }
        CP_COMMIT();
    };

    issue_stage(0, 0);

    for (int c = 0; c < CHUNKS; c++) {
        if (c + 1 < CHUNKS) {
            issue_stage(c + 1, (c + 1) & 1);
            CP_WAIT1();
        } else {
            CP_WAIT0();
        }
        __syncthreads();

        uint32_t bb = s0 + (c & 1) * STAGE_BYTES;
        uint32_t sA = bb, sB = bb + 8192;

        #pragma unroll
        for (int k16 = 0; k16 < 4; k16++) {
            uint32_t kb = (uint32_t)(k16 * 32);
            uint32_t af[2][4], bfr[2][4];
            #pragma unroll
            for (int mf = 0; mf < 2; mf++) {
                uint32_t ka = (kb + (uint32_t)aKext) ^ xr;
                ldm_x4(af[mf], sA + aBase[mf] + ka);
            }
            #pragma unroll
            for (int n2 = 0; n2 < 2; n2++) {
                uint32_t kbx = (kb + (uint32_t)bKext) ^ xr;
                ldm_x4(bfr[n2], sB + bBase[n2] + kbx);
            }
            #pragma unroll
            for (int mf = 0; mf < 2; mf++)
                #pragma unroll
                for (int nf = 0; nf < 4; nf++)
                    mma16816(acc[mf][nf], af[mf], bfr[nf >> 1][(nf & 1) * 2], bfr[nf >> 1][(nf & 1) * 2 + 1]);
        }
        __syncthreads();
    }

    if (MODE == 1) {
        // relu -> fp16, staged through smem stage-slot 0 (last compute used slot 1):
        //   chunk image loc (0/1) at s0 + loc*8192 (64 rows x 128B)
        #pragma unroll
        for (int mf = 0; mf < 2; mf++) {
            #pragma unroll
            for (int nf = 0; nf < 4; nf++) {
                int R0 = wm * 32 + mf * 16 + (lane >> 2);
                int nl = wn * 32 + nf * 8 + 2 * (lane & 3);
                int loc = nl >> 6, ncl = nl & 63;
                float c0 = fmaxf(acc[mf][nf][0], 0.0f);
                float c1 = fmaxf(acc[mf][nf][1], 0.0f);
                float c2 = fmaxf(acc[mf][nf][2], 0.0f);
                float c3 = fmaxf(acc[mf][nf][3], 0.0f);
                uint32_t off0 = SW128((uint32_t)(R0 * 128 + ncl * 2));
                uint32_t off1 = SW128((uint32_t)((R0 + 8) * 128 + ncl * 2));
                uint32_t base = s0 + loc * 8192;
                sts32(base + off0, pk16(f2h(c0), f2h(c1)));
                sts32(base + off1, pk16(f2h(c2), f2h(c3)));
            }
        }
        __syncthreads();
        const uint4* sh = (const uint4*)alp;
        #pragma unroll
        for (int i = tid; i < 1024; i += 256) {
            int cg = by * 2 + (i >> 9);
            size_t bidx = (size_t)(mt * 4 + cg) * 1024 + (size_t)rhalf * 512 + (i & 511);
            g_h1[bidx] = sh[i];
        }
    } else {
        // relu + fused layer-3 dot + atomic scatter (out pre-zeroed)
        #pragma unroll
        for (int mf = 0; mf < 2; mf++) {
            float s0v[3] = {0.f, 0.f, 0.f}, s1v[3] = {0.f, 0.f, 0.f};
            #pragma unroll
            for (int nf = 0; nf < 4; nf++) {
                float h0 = fmaxf(acc[mf][nf][0], 0.0f);
                float h1 = fmaxf(acc[mf][nf][1], 0.0f);
                float h2 = fmaxf(acc[mf][nf][2], 0.0f);
                float h3 = fmaxf(acc[mf][nf][3], 0.0f);
                #pragma unroll
                for (int j = 0; j < 3; j++) {
                    s0v[j] += h0 * w3r[nf][0][j] + h1 * w3r[nf][1][j];
                    s1v[j] += h2 * w3r[nf][0][j] + h3 * w3r[nf][1][j];
                }
            }
            #pragma unroll
            for (int j = 0; j < 3; j++) {
                #pragma unroll
                for (int off = 1; off <= 2; off <<= 1) {
                    s0v[j] += __shfl_xor_sync(0xFFFFFFFFu, s0v[j], off);
                    s1v[j] += __shfl_xor_sync(0xFFFFFFFFu, s1v[j], off);
                }
            }
            if ((lane & 3) == 0) {
                int R0 = wm * 32 + mf * 16 + (lane >> 2);
                int g0 = m0 + R0, g1 = g0 + 8;
                if (g0 < Mt) {
                    int v = p.idx[t][g0];
                    #pragma unroll
                    for (int j = 0; j < 3; j++) atomicAdd(&out[(size_t)v * 3 + j], s0v[j]);
                }
                if (g1 < Mt) {
                    int v = p.idx[t][g1];
                    #pragma unroll
                    for (int j = 0; j < 3; j++) atomicAdd(&out[(size_t)v * 3 + j], s1v[j]);
                }
            }
        }
    }
}

// ---------------------------------------------------------------------------
// Launch
// ---------------------------------------------------------------------------
#define GEMM_SMEM (2 * STAGE_BYTES + 1024)

extern "C" void kernel_launch(void* const* d_in, const int* in_sizes, int n_in,
                              void* d_out, int out_size) {
    const float* imgs     = (const float*)d_in[0];
    const float* pros     = (const float*)d_in[1];
    const float* x_verts  = (const float*)d_in[2];
    const float* W1       = (const float*)d_in[3];
    const float* W2       = (const float*)d_in[4];
    const float* W3       = (const float*)d_in[5];
    const int*   imgbatch = (const int*)d_in[6];
    const int*   gov      = (const int*)d_in[7];
    float*       out      = (float*)d_out;

    P p;
    p.rowOff[0] = 0;
    p.tileOff[0] = 0;
    for (int t = 0; t < NTYPES; t++) {
        p.idx[t] = (const int*)d_in[8 + t];
        p.M[t] = in_sizes[8 + t];
        p.rowOff[t + 1] = p.rowOff[t] + p.M[t];
        p.tileOff[t + 1] = p.tileOff[t] + (p.M[t] + 127) / 128;
    }
    int tiles = p.tileOff[NTYPES];

    cudaFuncSetAttribute(gemm_mma_kernel<2, 1>, cudaFuncAttributeMaxDynamicSharedMemorySize, GEMM_SMEM);
    cudaFuncSetAttribute(gemm_mma_kernel<4, 2>, cudaFuncAttributeMaxDynamicSharedMemorySize, GEMM_SMEM);

    // zero the output (layer-3 scatter accumulates with atomics)
    cudaMemsetAsync(d_out, 0, (size_t)out_size * sizeof(float), 0);

    dim3 gG(GARM, CCH);
    roi_garf_kernel<<<gG, 256>>>(imgs, pros, imgbatch);

    prep_kernel<<<tiles + 36 + 24, 256>>>(x_verts, W1, W2, gov, p, tiles);

    dim3 gM(2 * tiles, 2);
    gemm_mma_kernel<2, 1><<<gM, 256, GEMM_SMEM>>>(W3, gov, out, p);
    gemm_mma_kernel<4, 2><<<gM, 256, GEMM_SMEM>>>(W3, gov, out, p);
}